// round 15
// baseline (speedup 1.0000x reference)
#include <cuda_runtime.h>
#include <math.h>

// ---------------- problem constants ----------------
#define BB 2
#define PQ 1024
#define PJ 128
#define NBG 8

// ---------------- scratch (static device mem; no allocs) ----------------
__device__ float g_qT [NBG * PQ * 128];      // (bg, p, o)
__device__ float g_grid[NBG * PJ * 3];       // normalized grid_kv
__device__ float g_k  [BB * 8 * 64 * PJ];
__device__ float g_v  [BB * 8 * 64 * PJ];
__device__ float g_bias[2 * NBG * PQ * PJ];  // [m][n][i][j]
__device__ float g_attT[BB * PQ * 512];      // (b, p, c=h*64+d)

// ---------------- K1: grouped 1x1 conv -> qT only (coalesced, 1 barrier) ----------------
__global__ __launch_bounds__(128) void k_qproj(const float* __restrict__ x,
                                               const float* __restrict__ wq) {
    int bg = blockIdx.y;
    int p0 = blockIdx.x * 16;
    int o  = threadIdx.x;
    int b = bg >> 2, g = bg & 3;

    float wr[64];
    const float4* wrow = (const float4*)(wq + (g * 128 + o) * 64);
#pragma unroll
    for (int i = 0; i < 16; i++) {
        float4 v4 = wrow[i];
        wr[i*4+0] = v4.x; wr[i*4+1] = v4.y; wr[i*4+2] = v4.z; wr[i*4+3] = v4.w;
    }

    __shared__ __align__(16) float xs[16 * 68];
    const float* xb = x + (b * 256 + g * 64) * 1024 + p0;
    for (int idx = o; idx < 1024; idx += 128) {
        int i = idx >> 4, pp = idx & 15;
        xs[pp * 68 + i] = xb[i * 1024 + pp];
    }
    __syncthreads();

#pragma unroll
    for (int pp = 0; pp < 16; pp++) {
        const float4* x4 = (const float4*)(xs + pp * 68);
        float s = 0.f;
#pragma unroll
        for (int i4 = 0; i4 < 16; i4++) {
            float4 xv = x4[i4];
            s = fmaf(wr[i4*4+0], xv.x, s);
            s = fmaf(wr[i4*4+1], xv.y, s);
            s = fmaf(wr[i4*4+2], xv.z, s);
            s = fmaf(wr[i4*4+3], xv.w, s);
        }
        g_qT[(bg * 1024 + p0 + pp) * 128 + o] = s;
    }
}

// ---------------- K2+K3 fused: offsets (dwconv->GELU->pw->tanh->grid) + trilinear
//                  gather + k/v projection. Block = (n, jg of 8 j's). ----------------
__global__ __launch_bounds__(128) void k_offsample(const float* __restrict__ dww,
                                                   const float* __restrict__ dwb,
                                                   const float* __restrict__ pw,
                                                   const float* __restrict__ x,
                                                   const float* __restrict__ wk,
                                                   const float* __restrict__ wv) {
    int n  = blockIdx.y;
    int jg = blockIdx.x;                 // 0..15
    int b = n >> 2, g = n & 3;
    int c = threadIdx.x;                 // channel / thread id
    int lane = c & 31, warp = c >> 5;

    __shared__ float dws[64 * 129];      // dws[kidx*129 + c]
    __shared__ float part[12];
    __shared__ float grid_s[8][3];
    __shared__ float kvs[8][64];

    // prefetch sample-projection weights into registers (independent of phase A/B)
    float wkr[64], wvr[64];
    {
        const float4* wk4 = (const float4*)(wk + (g * 128 + c) * 64);
        const float4* wv4 = (const float4*)(wv + (g * 128 + c) * 64);
#pragma unroll
        for (int i = 0; i < 16; i++) {
            float4 a = wk4[i], c4 = wv4[i];
            wkr[i*4+0] = a.x;  wkr[i*4+1] = a.y;  wkr[i*4+2] = a.z;  wkr[i*4+3] = a.w;
            wvr[i*4+0] = c4.x; wvr[i*4+1] = c4.y; wvr[i*4+2] = c4.z; wvr[i*4+3] = c4.w;
        }
    }

    // phase A: stage depthwise weights transposed (once per block, serves 8 j's)
    for (int idx = c; idx < 8192; idx += 128) {
        int cc = idx >> 6, kk = idx & 63;
        dws[kk * 129 + cc] = dww[idx];
    }
    float dwbc = dwb[c];
    float pw0 = pw[c], pw1 = pw[128 + c], pw2 = pw[256 + c];
    __syncthreads();

    // phase B: offsets for 8 output positions
    const float* qb = g_qT + n * 1024 * 128;
    for (int jl = 0; jl < 8; jl++) {
        int jj = jg * 8 + jl;
        int od = jj >> 6, oh = (jj >> 3) & 7, ow = jj & 7;

        float acc = 0.f;
#pragma unroll
        for (int kf = 0; kf < 4; kf++) {
            int fi = od * 2 - 1 + kf;
            if (fi < 0 || fi >= 4) continue;
#pragma unroll
            for (int kh = 0; kh < 4; kh++) {
                int hi = oh * 2 - 1 + kh;
                if (hi < 0 || hi >= 16) continue;
#pragma unroll
                for (int kw = 0; kw < 4; kw++) {
                    int wi = ow * 2 - 1 + kw;
                    if (wi < 0 || wi >= 16) continue;
                    int sp = fi * 256 + hi * 16 + wi;
                    acc = fmaf(qb[sp * 128 + c], dws[(kf * 16 + kh * 4 + kw) * 129 + c], acc);
                }
            }
        }
        float v  = acc + dwbc;
        float ge = 0.5f * v * (1.0f + erff(v * 0.70710678118654752f));   // exact GELU

        float r0 = ge * pw0, r1 = ge * pw1, r2 = ge * pw2;
#pragma unroll
        for (int o = 16; o > 0; o >>= 1) {
            r0 += __shfl_xor_sync(0xffffffff, r0, o);
            r1 += __shfl_xor_sync(0xffffffff, r1, o);
            r2 += __shfl_xor_sync(0xffffffff, r2, o);
        }
        if (lane == 0) { part[warp * 3 + 0] = r0; part[warp * 3 + 1] = r1; part[warp * 3 + 2] = r2; }
        __syncthreads();
        if (c < 3) {
            float tot = part[c] + part[3 + c] + part[6 + c] + part[9 + c];
            float off = tanhf(tot) * 2.0f;
            float basec = (c == 0) ? (float)od : (c == 1) ? (float)oh : (float)ow;
            float denom = (c == 0) ? 1.0f : 7.0f;
            float gval = 2.0f * (basec + off) / denom - 1.0f;
            grid_s[jl][c] = gval;
            g_grid[(n * 128 + jj) * 3 + c] = gval;      // consumed by k_cpb
        }
        __syncthreads();
    }

    // phase C: trilinear gather for the 8 j's
    for (int u = c; u < 512; u += 128) {
        int jl = u >> 6, ch = u & 63;
        float g0 = grid_s[jl][0];
        float g1 = grid_s[jl][1];
        float g2 = grid_s[jl][2];
        // grid_sample axis convention: comp0->W(16), comp1->H(16), comp2->D(4)
        float ix = ((g0 + 1.f) * 16.f - 1.f) * 0.5f;
        float iy = ((g1 + 1.f) * 16.f - 1.f) * 0.5f;
        float iz = ((g2 + 1.f) * 4.f  - 1.f) * 0.5f;
        float x0f = floorf(ix), y0f = floorf(iy), z0f = floorf(iz);
        float tx = ix - x0f, ty = iy - y0f, tz = iz - z0f;
        int x0 = (int)x0f, y0 = (int)y0f, z0 = (int)z0f;

        const float* vol = x + (b * 256 + g * 64 + ch) * 1024;
        float s = 0.f;
#pragma unroll
        for (int dz = 0; dz < 2; dz++)
#pragma unroll
            for (int dy = 0; dy < 2; dy++)
#pragma unroll
                for (int dx = 0; dx < 2; dx++) {
                    int xc = x0 + dx, yc = y0 + dy, zc = z0 + dz;
                    float wgt = (dx ? tx : 1.f - tx) * (dy ? ty : 1.f - ty) * (dz ? tz : 1.f - tz);
                    if (xc >= 0 && xc < 16 && yc >= 0 && yc < 16 && zc >= 0 && zc < 4)
                        s = fmaf(vol[zc * 256 + yc * 16 + xc], wgt, s);
                }
        kvs[jl][ch] = s;
    }
    __syncthreads();

    // k/v projection: output row c, 8 j's, weights in registers
    int h = g * 2 + (c >> 6);
    int d = c & 63;
    float* kout = g_k + ((b * 8 + h) * 64 + d) * 128 + jg * 8;
    float* vout = g_v + ((b * 8 + h) * 64 + d) * 128 + jg * 8;
    for (int jl = 0; jl < 8; jl++) {
        float sk = 0.f, sv = 0.f;
#pragma unroll
        for (int i = 0; i < 64; i++) {
            float kv = kvs[jl][i];            // broadcast LDS
            sk = fmaf(kv, wkr[i], sk);
            sv = fmaf(kv, wvr[i], sv);
        }
        kout[jl] = sk;
        vout[jl] = sv;
    }
}

// ---------------- K4: CPB bias MLP — f32x2 packed, 2 pairs/thread (best measured: 200us) ----------------
__global__ __launch_bounds__(256, 1) void k_cpb(const float* __restrict__ w0,
                                                const float* __restrict__ b0,
                                                const float* __restrict__ w1,
                                                const float* __restrict__ b1,
                                                const float* __restrict__ w2,
                                                const float* __restrict__ b2) {
    __shared__ __align__(16) float w1s[4096];
    __shared__ float w0s[192], b0s[64], b1s[64], w2s[128], b2s[2];
    int tid = threadIdx.x;
    for (int i = tid; i < 192;  i += 256) w0s[i] = w0[i];
    for (int i = tid; i < 64;   i += 256) { b0s[i] = b0[i]; b1s[i] = b1[i]; }
    for (int i = tid; i < 4096; i += 256) w1s[i] = w1[i];
    for (int i = tid; i < 128;  i += 256) w2s[i] = w2[i];
    if (tid < 2) b2s[tid] = b2[tid];
    __syncthreads();

    int pa = blockIdx.x * 512 + tid;
    int pb = pa + 256;

    float ta0, ta1, ta2, tb0, tb1, tb2;
    {
        int n = pa >> 17, i = (pa >> 7) & 1023, j = pa & 127;
        float gq0 = 2.f * (float)(i >> 8)        / 3.f  - 1.f;
        float gq1 = 2.f * (float)((i >> 4) & 15) / 15.f - 1.f;
        float gq2 = 2.f * (float)(i & 15)        / 15.f - 1.f;
        float p0 = gq0 - g_grid[(n * 128 + j) * 3 + 0];
        float p1 = gq1 - g_grid[(n * 128 + j) * 3 + 1];
        float p2 = gq2 - g_grid[(n * 128 + j) * 3 + 2];
        ta0 = copysignf(log1pf(fabsf(p0)), p0);
        ta1 = copysignf(log1pf(fabsf(p1)), p1);
        ta2 = copysignf(log1pf(fabsf(p2)), p2);
    }
    {
        int n = pb >> 17, i = (pb >> 7) & 1023, j = pb & 127;
        float gq0 = 2.f * (float)(i >> 8)        / 3.f  - 1.f;
        float gq1 = 2.f * (float)((i >> 4) & 15) / 15.f - 1.f;
        float gq2 = 2.f * (float)(i & 15)        / 15.f - 1.f;
        float p0 = gq0 - g_grid[(n * 128 + j) * 3 + 0];
        float p1 = gq1 - g_grid[(n * 128 + j) * 3 + 1];
        float p2 = gq2 - g_grid[(n * 128 + j) * 3 + 2];
        tb0 = copysignf(log1pf(fabsf(p0)), p0);
        tb1 = copysignf(log1pf(fabsf(p1)), p1);
        tb2 = copysignf(log1pf(fabsf(p2)), p2);
    }

    unsigned long long acc_a[32], acc_b[32];
#pragma unroll
    for (int c = 0; c < 32; c++) {
        unsigned long long bi;
        asm("mov.b64 %0, {%1, %2};" : "=l"(bi) : "f"(b1s[2 * c]), "f"(b1s[2 * c + 1]));
        acc_a[c] = bi;
        acc_b[c] = bi;
    }

#pragma unroll 4
    for (int k = 0; k < 64; k++) {
        float w0k = w0s[k], w1k = w0s[64 + k], w2k = w0s[128 + k], b0k = b0s[k];
        float ha = fmaxf(fmaf(ta0, w0k, fmaf(ta1, w1k, fmaf(ta2, w2k, b0k))), 0.f);
        float hb = fmaxf(fmaf(tb0, w0k, fmaf(tb1, w1k, fmaf(tb2, w2k, b0k))), 0.f);
        unsigned long long ha2, hb2;
        asm("mov.b64 %0, {%1, %1};" : "=l"(ha2) : "f"(ha));
        asm("mov.b64 %0, {%1, %1};" : "=l"(hb2) : "f"(hb));
        const ulonglong2* wrow = (const ulonglong2*)(w1s + k * 64);
#pragma unroll
        for (int c = 0; c < 16; c++) {
            ulonglong2 wv = wrow[c];
            asm("fma.rn.f32x2 %0, %1, %2, %0;" : "+l"(acc_a[2 * c])     : "l"(ha2), "l"(wv.x));
            asm("fma.rn.f32x2 %0, %1, %2, %0;" : "+l"(acc_a[2 * c + 1]) : "l"(ha2), "l"(wv.y));
            asm("fma.rn.f32x2 %0, %1, %2, %0;" : "+l"(acc_b[2 * c])     : "l"(hb2), "l"(wv.x));
            asm("fma.rn.f32x2 %0, %1, %2, %0;" : "+l"(acc_b[2 * c + 1]) : "l"(hb2), "l"(wv.y));
        }
    }

    {
        float o0 = b2s[0], o1 = b2s[1];
#pragma unroll
        for (int c = 0; c < 32; c++) {
            float lo, hi;
            asm("mov.b64 {%0, %1}, %2;" : "=f"(lo), "=f"(hi) : "l"(acc_a[c]));
            lo = fmaxf(lo, 0.f); hi = fmaxf(hi, 0.f);
            o0 = fmaf(lo, w2s[4 * c + 0], o0);
            o1 = fmaf(lo, w2s[4 * c + 1], o1);
            o0 = fmaf(hi, w2s[4 * c + 2], o0);
            o1 = fmaf(hi, w2s[4 * c + 3], o1);
        }
        int n = pa >> 17, i = (pa >> 7) & 1023, j = pa & 127;
        g_bias[(        n * 1024 + i) * 128 + j] = o0;
        g_bias[((8 + n) * 1024 + i) * 128 + j]   = o1;
    }
    {
        float o0 = b2s[0], o1 = b2s[1];
#pragma unroll
        for (int c = 0; c < 32; c++) {
            float lo, hi;
            asm("mov.b64 {%0, %1}, %2;" : "=f"(lo), "=f"(hi) : "l"(acc_b[c]));
            lo = fmaxf(lo, 0.f); hi = fmaxf(hi, 0.f);
            o0 = fmaf(lo, w2s[4 * c + 0], o0);
            o1 = fmaf(lo, w2s[4 * c + 1], o1);
            o0 = fmaf(hi, w2s[4 * c + 2], o0);
            o1 = fmaf(hi, w2s[4 * c + 3], o1);
        }
        int n = pb >> 17, i = (pb >> 7) & 1023, j = pb & 127;
        g_bias[(        n * 1024 + i) * 128 + j] = o0;
        g_bias[((8 + n) * 1024 + i) * 128 + j]   = o1;
    }
}

// ---------------- K5: attention — 4 i-rows per round, K in registers ----------------
__global__ __launch_bounds__(128) void k_attn() {
    int b = blockIdx.z, h = blockIdx.y;
    int i0 = blockIdx.x * 32;
    int g = h >> 1, m = h & 1;
    int n = b * 4 + g;
    int t = threadIdx.x;
    int lane = t & 31, warp = t >> 5;

    __shared__ float vs[64 * 129];
    __shared__ __align__(16) float qs[4][64];
    __shared__ __align__(16) float attn4[128][4];
    __shared__ float wredm[4][4], wreds[4][4];
    __shared__ float ored[4][128];

    const float* kb = g_k + (b * 8 + h) * 64 * 128;
    const float* vb = g_v + (b * 8 + h) * 64 * 128;

    float kreg[64];
#pragma unroll
    for (int d = 0; d < 64; d++) kreg[d] = kb[d * 128 + t];

    for (int idx = t; idx < 8192; idx += 128) {
        int d = idx >> 7, jc = idx & 127;
        vs[d * 129 + jc] = vb[idx];
    }
    const float* biasrow = g_bias + ((m * 8 + n) * 1024) * 128;
    const float* qbase = g_qT + ((b * 4 + g) * 1024) * 128 + m * 64;

    for (int ii = 0; ii < 32; ii += 4) {
        __syncthreads();
        for (int idx = t; idx < 256; idx += 128) {
            int iq = idx >> 6, d = idx & 63;
            qs[iq][d] = qbase[(i0 + ii + iq) * 128 + d];
        }
        __syncthreads();

        float s[4];
#pragma unroll
        for (int iq = 0; iq < 4; iq++) {
            const float4* q4 = (const float4*)qs[iq];
            float acc = 0.f;
#pragma unroll
            for (int dd = 0; dd < 16; dd++) {
                float4 qv = q4[dd];
                acc = fmaf(qv.x, kreg[dd * 4 + 0], acc);
                acc = fmaf(qv.y, kreg[dd * 4 + 1], acc);
                acc = fmaf(qv.z, kreg[dd * 4 + 2], acc);
                acc = fmaf(qv.w, kreg[dd * 4 + 3], acc);
            }
            s[iq] = fmaf(acc, 0.125f, biasrow[(i0 + ii + iq) * 128 + t]);
        }

        float lm[4];
#pragma unroll
        for (int iq = 0; iq < 4; iq++) lm[iq] = s[iq];
#pragma unroll
        for (int o = 16; o > 0; o >>= 1)
#pragma unroll
            for (int iq = 0; iq < 4; iq++)
                lm[iq] = fmaxf(lm[iq], __shfl_xor_sync(0xffffffff, lm[iq], o));
        if (lane == 0)
#pragma unroll
            for (int iq = 0; iq < 4; iq++) wredm[iq][warp] = lm[iq];
        __syncthreads();

        float e[4], ls[4];
#pragma unroll
        for (int iq = 0; iq < 4; iq++) {
            float mx = fmaxf(fmaxf(wredm[iq][0], wredm[iq][1]),
                             fmaxf(wredm[iq][2], wredm[iq][3]));
            e[iq] = __expf(s[iq] - mx);
            ls[iq] = e[iq];
        }
        *(float4*)attn4[t] = make_float4(e[0], e[1], e[2], e[3]);
#pragma unroll
        for (int o = 16; o > 0; o >>= 1)
#pragma unroll
            for (int iq = 0; iq < 4; iq++)
                ls[iq] += __shfl_xor_sync(0xffffffff, ls[iq], o);
        if (lane == 0)
#pragma unroll
            for (int iq = 0; iq < 4; iq++) wreds[iq][warp] = ls[iq];
        __syncthreads();

        float inv[4];
#pragma unroll
        for (int iq = 0; iq < 4; iq++)
            inv[iq] = 1.f / (wreds[iq][0] + wreds[iq][1] + wreds[iq][2] + wreds[iq][3]);

        int d = t & 63, half = t >> 6;
        const float*  vrow = vs + d * 129 + half * 64;
        const float4* arow = (const float4*)attn4[half * 64];
        float a0 = 0.f, a1 = 0.f, a2 = 0.f, a3 = 0.f;
#pragma unroll
        for (int jj = 0; jj < 64; jj++) {
            float  vv = vrow[jj];
            float4 av = arow[jj];
            a0 = fmaf(av.x, vv, a0);
            a1 = fmaf(av.y, vv, a1);
            a2 = fmaf(av.z, vv, a2);
            a3 = fmaf(av.w, vv, a3);
        }
        ored[0][t] = a0; ored[1][t] = a1; ored[2][t] = a2; ored[3][t] = a3;
        __syncthreads();
        if (t < 64) {
#pragma unroll
            for (int iq = 0; iq < 4; iq++)
                g_attT[(b * 1024 + i0 + ii + iq) * 512 + h * 64 + t] =
                    (ored[iq][t] + ored[iq][64 + t]) * inv[iq];
        }
    }
}

// ---------------- K6: output projection — 2x2 register blocking ----------------
__global__ __launch_bounds__(256) void k_outproj(const float* __restrict__ wo,
                                                 const float* __restrict__ bo,
                                                 float* __restrict__ out) {
    int b  = blockIdx.z;
    int ty = threadIdx.y, tx = threadIdx.x;
    int o0 = blockIdx.y * 32;
    int p0 = blockIdx.x * 32;

    __shared__ float wos[32][17];
    __shared__ float ats[32][17];
    float a00 = 0.f, a01 = 0.f, a10 = 0.f, a11 = 0.f;
    for (int kt = 0; kt < 32; kt++) {
        wos[ty]     [tx] = wo[(o0 + ty)      * 512 + kt * 16 + tx];
        wos[ty + 16][tx] = wo[(o0 + ty + 16) * 512 + kt * 16 + tx];
        ats[ty]     [tx] = g_attT[(b * 1024 + p0 + ty)      * 512 + kt * 16 + tx];
        ats[ty + 16][tx] = g_attT[(b * 1024 + p0 + ty + 16) * 512 + kt * 16 + tx];
        __syncthreads();
#pragma unroll
        for (int kk = 0; kk < 16; kk++) {
            float wa = wos[ty][kk],      wb2 = wos[ty + 16][kk];
            float pa = ats[tx][kk],      pb  = ats[tx + 16][kk];
            a00 = fmaf(wa,  pa, a00);
            a01 = fmaf(wa,  pb, a01);
            a10 = fmaf(wb2, pa, a10);
            a11 = fmaf(wb2, pb, a11);
        }
        __syncthreads();
    }
    float bo0 = bo[o0 + ty], bo1 = bo[o0 + ty + 16];
    out[(b * 256 + o0 + ty)      * 1024 + p0 + tx]      = a00 + bo0;
    out[(b * 256 + o0 + ty)      * 1024 + p0 + tx + 16] = a01 + bo0;
    out[(b * 256 + o0 + ty + 16) * 1024 + p0 + tx]      = a10 + bo1;
    out[(b * 256 + o0 + ty + 16) * 1024 + p0 + tx + 16] = a11 + bo1;
}

// ---------------- launch ----------------
extern "C" void kernel_launch(void* const* d_in, const int* in_sizes, int n_in,
                              void* d_out, int out_size) {
    const float* x      = (const float*)d_in[0];
    const float* wq     = (const float*)d_in[1];
    const float* wk     = (const float*)d_in[2];
    const float* wv     = (const float*)d_in[3];
    const float* dww    = (const float*)d_in[4];
    const float* dwb    = (const float*)d_in[5];
    const float* pw     = (const float*)d_in[6];
    const float* cw0    = (const float*)d_in[7];
    const float* cb0    = (const float*)d_in[8];
    const float* cw1    = (const float*)d_in[9];
    const float* cb1    = (const float*)d_in[10];
    const float* cw2    = (const float*)d_in[11];
    const float* cb2    = (const float*)d_in[12];
    const float* wo     = (const float*)d_in[13];
    const float* bo     = (const float*)d_in[14];
    float* out = (float*)d_out;

    k_qproj    <<<dim3(64, 8),       128>>>(x, wq);
    k_offsample<<<dim3(16, 8),       128>>>(dww, dwb, pw, x, wk, wv);
    k_cpb      <<<2048,              256>>>(cw0, cb0, cw1, cb1, cw2, cb2);
    k_attn     <<<dim3(32, 8, 2),    128>>>();
    k_outproj  <<<dim3(32, 8, 2), dim3(16, 16)>>>(wo, bo, out);
}

// round 16
// speedup vs baseline: 1.0274x; 1.0274x over previous
#include <cuda_runtime.h>
#include <math.h>

// ---------------- problem constants ----------------
#define BB 2
#define PQ 1024
#define PJ 128
#define NBG 8

// ---------------- scratch (static device mem; no allocs) ----------------
__device__ float g_qT [NBG * PQ * 128];      // (bg, p, o)
__device__ float g_grid[NBG * PJ * 3];       // normalized grid_kv
__device__ float g_k  [BB * 8 * 64 * PJ];
__device__ float g_v  [BB * 8 * 64 * PJ];
__device__ float g_bias[2 * NBG * PQ * PJ];  // [m][n][i][j]
__device__ float g_attT[BB * PQ * 512];      // (b, p, c=h*64+d)

// ---------------- K1: grouped 1x1 conv -> qT only (coalesced, 1 barrier) ----------------
__global__ __launch_bounds__(128) void k_qproj(const float* __restrict__ x,
                                               const float* __restrict__ wq) {
    int bg = blockIdx.y;
    int p0 = blockIdx.x * 16;
    int o  = threadIdx.x;
    int b = bg >> 2, g = bg & 3;

    float wr[64];
    const float4* wrow = (const float4*)(wq + (g * 128 + o) * 64);
#pragma unroll
    for (int i = 0; i < 16; i++) {
        float4 v4 = wrow[i];
        wr[i*4+0] = v4.x; wr[i*4+1] = v4.y; wr[i*4+2] = v4.z; wr[i*4+3] = v4.w;
    }

    __shared__ __align__(16) float xs[16 * 68];
    const float* xb = x + (b * 256 + g * 64) * 1024 + p0;
    for (int idx = o; idx < 1024; idx += 128) {
        int i = idx >> 4, pp = idx & 15;
        xs[pp * 68 + i] = xb[i * 1024 + pp];
    }
    __syncthreads();

#pragma unroll
    for (int pp = 0; pp < 16; pp++) {
        const float4* x4 = (const float4*)(xs + pp * 68);
        float s = 0.f;
#pragma unroll
        for (int i4 = 0; i4 < 16; i4++) {
            float4 xv = x4[i4];
            s = fmaf(wr[i4*4+0], xv.x, s);
            s = fmaf(wr[i4*4+1], xv.y, s);
            s = fmaf(wr[i4*4+2], xv.z, s);
            s = fmaf(wr[i4*4+3], xv.w, s);
        }
        g_qT[(bg * 1024 + p0 + pp) * 128 + o] = s;
    }
}

// ---------------- K2: depthwise conv (coalesced via qT) -> GELU -> pw -> tanh -> grid ----------------
__global__ __launch_bounds__(128) void k_offsets(const float* __restrict__ dww,
                                                 const float* __restrict__ dwb,
                                                 const float* __restrict__ pw) {
    int n  = blockIdx.y;
    int jj = blockIdx.x;
    int od = jj >> 6, oh = (jj >> 3) & 7, ow = jj & 7;
    int c  = threadIdx.x;
    int lane = c & 31, warp = c >> 5;

    __shared__ float dws[64 * 129];
    __shared__ float part[12];
    for (int idx = c; idx < 8192; idx += 128) {
        int cc = idx >> 6, kk = idx & 63;
        dws[kk * 129 + cc] = dww[idx];
    }
    __syncthreads();

    const float* qb = g_qT + n * 1024 * 128;
    float acc = 0.f;
#pragma unroll
    for (int kf = 0; kf < 4; kf++) {
        int fi = od * 2 - 1 + kf;
        if (fi < 0 || fi >= 4) continue;
#pragma unroll
        for (int kh = 0; kh < 4; kh++) {
            int hi = oh * 2 - 1 + kh;
            if (hi < 0 || hi >= 16) continue;
#pragma unroll
            for (int kw = 0; kw < 4; kw++) {
                int wi = ow * 2 - 1 + kw;
                if (wi < 0 || wi >= 16) continue;
                int sp = fi * 256 + hi * 16 + wi;
                acc = fmaf(qb[sp * 128 + c], dws[(kf * 16 + kh * 4 + kw) * 129 + c], acc);
            }
        }
    }
    float v  = acc + dwb[c];
    float ge = 0.5f * v * (1.0f + erff(v * 0.70710678118654752f));   // exact GELU

    float r0 = ge * pw[c], r1 = ge * pw[128 + c], r2 = ge * pw[256 + c];
#pragma unroll
    for (int o = 16; o > 0; o >>= 1) {
        r0 += __shfl_xor_sync(0xffffffff, r0, o);
        r1 += __shfl_xor_sync(0xffffffff, r1, o);
        r2 += __shfl_xor_sync(0xffffffff, r2, o);
    }
    if (lane == 0) { part[warp * 3 + 0] = r0; part[warp * 3 + 1] = r1; part[warp * 3 + 2] = r2; }
    __syncthreads();
    if (c < 3) {
        float tot = part[c] + part[3 + c] + part[6 + c] + part[9 + c];
        float off = tanhf(tot) * 2.0f;
        float basec = (c == 0) ? (float)od : (c == 1) ? (float)oh : (float)ow;
        float denom = (c == 0) ? 1.0f : 7.0f;
        g_grid[(n * 128 + jj) * 3 + c] = 2.0f * (basec + off) / denom - 1.0f;
    }
}

// ---------------- K3: trilinear gather + k/v projection (8 j per block, weights in regs) ----------------
__global__ __launch_bounds__(128) void k_sample(const float* __restrict__ x,
                                                const float* __restrict__ wk,
                                                const float* __restrict__ wv) {
    int n  = blockIdx.y;
    int jg = blockIdx.x;
    int b = n >> 2, g = n & 3;
    int t = threadIdx.x;

    float wkr[64], wvr[64];
    {
        const float4* wk4 = (const float4*)(wk + (g * 128 + t) * 64);
        const float4* wv4 = (const float4*)(wv + (g * 128 + t) * 64);
#pragma unroll
        for (int i = 0; i < 16; i++) {
            float4 a = wk4[i], c4 = wv4[i];
            wkr[i*4+0] = a.x;  wkr[i*4+1] = a.y;  wkr[i*4+2] = a.z;  wkr[i*4+3] = a.w;
            wvr[i*4+0] = c4.x; wvr[i*4+1] = c4.y; wvr[i*4+2] = c4.z; wvr[i*4+3] = c4.w;
        }
    }

    __shared__ float kvs[8][64];
    for (int u = t; u < 512; u += 128) {
        int jl = u >> 6, c = u & 63;
        int j = jg * 8 + jl;
        float g0 = g_grid[(n * 128 + j) * 3 + 0];
        float g1 = g_grid[(n * 128 + j) * 3 + 1];
        float g2 = g_grid[(n * 128 + j) * 3 + 2];
        float ix = ((g0 + 1.f) * 16.f - 1.f) * 0.5f;
        float iy = ((g1 + 1.f) * 16.f - 1.f) * 0.5f;
        float iz = ((g2 + 1.f) * 4.f  - 1.f) * 0.5f;
        float x0f = floorf(ix), y0f = floorf(iy), z0f = floorf(iz);
        float tx = ix - x0f, ty = iy - y0f, tz = iz - z0f;
        int x0 = (int)x0f, y0 = (int)y0f, z0 = (int)z0f;

        const float* vol = x + (b * 256 + g * 64 + c) * 1024;
        float s = 0.f;
#pragma unroll
        for (int dz = 0; dz < 2; dz++)
#pragma unroll
            for (int dy = 0; dy < 2; dy++)
#pragma unroll
                for (int dx = 0; dx < 2; dx++) {
                    int xc = x0 + dx, yc = y0 + dy, zc = z0 + dz;
                    float wgt = (dx ? tx : 1.f - tx) * (dy ? ty : 1.f - ty) * (dz ? tz : 1.f - tz);
                    if (xc >= 0 && xc < 16 && yc >= 0 && yc < 16 && zc >= 0 && zc < 4)
                        s = fmaf(vol[zc * 256 + yc * 16 + xc], wgt, s);
                }
        kvs[jl][c] = s;
    }
    __syncthreads();

    int h = g * 2 + (t >> 6);
    int d = t & 63;
    float* kout = g_k + ((b * 8 + h) * 64 + d) * 128 + jg * 8;
    float* vout = g_v + ((b * 8 + h) * 64 + d) * 128 + jg * 8;
    for (int jl = 0; jl < 8; jl++) {
        float sk = 0.f, sv = 0.f;
#pragma unroll
        for (int i = 0; i < 64; i++) {
            float kv = kvs[jl][i];
            sk = fmaf(kv, wkr[i], sk);
            sv = fmaf(kv, wvr[i], sv);
        }
        kout[jl] = sk;
        vout[jl] = sv;
    }
}

// ---------------- K4: CPB bias MLP — f32x2 packed, 2 pairs/thread (best measured: 200us) ----------------
__global__ __launch_bounds__(256, 1) void k_cpb(const float* __restrict__ w0,
                                                const float* __restrict__ b0,
                                                const float* __restrict__ w1,
                                                const float* __restrict__ b1,
                                                const float* __restrict__ w2,
                                                const float* __restrict__ b2) {
    __shared__ __align__(16) float w1s[4096];
    __shared__ float w0s[192], b0s[64], b1s[64], w2s[128], b2s[2];
    int tid = threadIdx.x;
    for (int i = tid; i < 192;  i += 256) w0s[i] = w0[i];
    for (int i = tid; i < 64;   i += 256) { b0s[i] = b0[i]; b1s[i] = b1[i]; }
    for (int i = tid; i < 4096; i += 256) w1s[i] = w1[i];
    for (int i = tid; i < 128;  i += 256) w2s[i] = w2[i];
    if (tid < 2) b2s[tid] = b2[tid];
    __syncthreads();

    int pa = blockIdx.x * 512 + tid;
    int pb = pa + 256;

    float ta0, ta1, ta2, tb0, tb1, tb2;
    {
        int n = pa >> 17, i = (pa >> 7) & 1023, j = pa & 127;
        float gq0 = 2.f * (float)(i >> 8)        / 3.f  - 1.f;
        float gq1 = 2.f * (float)((i >> 4) & 15) / 15.f - 1.f;
        float gq2 = 2.f * (float)(i & 15)        / 15.f - 1.f;
        float p0 = gq0 - g_grid[(n * 128 + j) * 3 + 0];
        float p1 = gq1 - g_grid[(n * 128 + j) * 3 + 1];
        float p2 = gq2 - g_grid[(n * 128 + j) * 3 + 2];
        ta0 = copysignf(log1pf(fabsf(p0)), p0);
        ta1 = copysignf(log1pf(fabsf(p1)), p1);
        ta2 = copysignf(log1pf(fabsf(p2)), p2);
    }
    {
        int n = pb >> 17, i = (pb >> 7) & 1023, j = pb & 127;
        float gq0 = 2.f * (float)(i >> 8)        / 3.f  - 1.f;
        float gq1 = 2.f * (float)((i >> 4) & 15) / 15.f - 1.f;
        float gq2 = 2.f * (float)(i & 15)        / 15.f - 1.f;
        float p0 = gq0 - g_grid[(n * 128 + j) * 3 + 0];
        float p1 = gq1 - g_grid[(n * 128 + j) * 3 + 1];
        float p2 = gq2 - g_grid[(n * 128 + j) * 3 + 2];
        tb0 = copysignf(log1pf(fabsf(p0)), p0);
        tb1 = copysignf(log1pf(fabsf(p1)), p1);
        tb2 = copysignf(log1pf(fabsf(p2)), p2);
    }

    unsigned long long acc_a[32], acc_b[32];
#pragma unroll
    for (int c = 0; c < 32; c++) {
        unsigned long long bi;
        asm("mov.b64 %0, {%1, %2};" : "=l"(bi) : "f"(b1s[2 * c]), "f"(b1s[2 * c + 1]));
        acc_a[c] = bi;
        acc_b[c] = bi;
    }

#pragma unroll 4
    for (int k = 0; k < 64; k++) {
        float w0k = w0s[k], w1k = w0s[64 + k], w2k = w0s[128 + k], b0k = b0s[k];
        float ha = fmaxf(fmaf(ta0, w0k, fmaf(ta1, w1k, fmaf(ta2, w2k, b0k))), 0.f);
        float hb = fmaxf(fmaf(tb0, w0k, fmaf(tb1, w1k, fmaf(tb2, w2k, b0k))), 0.f);
        unsigned long long ha2, hb2;
        asm("mov.b64 %0, {%1, %1};" : "=l"(ha2) : "f"(ha));
        asm("mov.b64 %0, {%1, %1};" : "=l"(hb2) : "f"(hb));
        const ulonglong2* wrow = (const ulonglong2*)(w1s + k * 64);
#pragma unroll
        for (int c = 0; c < 16; c++) {
            ulonglong2 wv = wrow[c];
            asm("fma.rn.f32x2 %0, %1, %2, %0;" : "+l"(acc_a[2 * c])     : "l"(ha2), "l"(wv.x));
            asm("fma.rn.f32x2 %0, %1, %2, %0;" : "+l"(acc_a[2 * c + 1]) : "l"(ha2), "l"(wv.y));
            asm("fma.rn.f32x2 %0, %1, %2, %0;" : "+l"(acc_b[2 * c])     : "l"(hb2), "l"(wv.x));
            asm("fma.rn.f32x2 %0, %1, %2, %0;" : "+l"(acc_b[2 * c + 1]) : "l"(hb2), "l"(wv.y));
        }
    }

    {
        float o0 = b2s[0], o1 = b2s[1];
#pragma unroll
        for (int c = 0; c < 32; c++) {
            float lo, hi;
            asm("mov.b64 {%0, %1}, %2;" : "=f"(lo), "=f"(hi) : "l"(acc_a[c]));
            lo = fmaxf(lo, 0.f); hi = fmaxf(hi, 0.f);
            o0 = fmaf(lo, w2s[4 * c + 0], o0);
            o1 = fmaf(lo, w2s[4 * c + 1], o1);
            o0 = fmaf(hi, w2s[4 * c + 2], o0);
            o1 = fmaf(hi, w2s[4 * c + 3], o1);
        }
        int n = pa >> 17, i = (pa >> 7) & 1023, j = pa & 127;
        g_bias[(        n * 1024 + i) * 128 + j] = o0;
        g_bias[((8 + n) * 1024 + i) * 128 + j]   = o1;
    }
    {
        float o0 = b2s[0], o1 = b2s[1];
#pragma unroll
        for (int c = 0; c < 32; c++) {
            float lo, hi;
            asm("mov.b64 {%0, %1}, %2;" : "=f"(lo), "=f"(hi) : "l"(acc_b[c]));
            lo = fmaxf(lo, 0.f); hi = fmaxf(hi, 0.f);
            o0 = fmaf(lo, w2s[4 * c + 0], o0);
            o1 = fmaf(lo, w2s[4 * c + 1], o1);
            o0 = fmaf(hi, w2s[4 * c + 2], o0);
            o1 = fmaf(hi, w2s[4 * c + 3], o1);
        }
        int n = pb >> 17, i = (pb >> 7) & 1023, j = pb & 127;
        g_bias[(        n * 1024 + i) * 128 + j] = o0;
        g_bias[((8 + n) * 1024 + i) * 128 + j]   = o1;
    }
}

// ---------------- K5: attention — 8 i-rows per round, K in registers ----------------
__global__ __launch_bounds__(128) void k_attn() {
    int b = blockIdx.z, h = blockIdx.y;
    int i0 = blockIdx.x * 32;
    int g = h >> 1, m = h & 1;
    int n = b * 4 + g;
    int t = threadIdx.x;
    int lane = t & 31, warp = t >> 5;

    __shared__ float vs[64 * 129];
    __shared__ __align__(16) float qs[8][64];
    __shared__ __align__(16) float attn8[128][8];   // [j][iq]
    __shared__ float wredm[8][4], wreds[8][4];
    __shared__ float ored[8][128];

    const float* kb = g_k + (b * 8 + h) * 64 * 128;
    const float* vb = g_v + (b * 8 + h) * 64 * 128;

    float kreg[64];
#pragma unroll
    for (int d = 0; d < 64; d++) kreg[d] = kb[d * 128 + t];

    for (int idx = t; idx < 8192; idx += 128) {
        int d = idx >> 7, jc = idx & 127;
        vs[d * 129 + jc] = vb[idx];
    }
    const float* biasrow = g_bias + ((m * 8 + n) * 1024) * 128;
    const float* qbase = g_qT + ((b * 4 + g) * 1024) * 128 + m * 64;

    for (int ii = 0; ii < 32; ii += 8) {
        __syncthreads();                     // guard qs/attn8/ored reuse
        for (int idx = t; idx < 512; idx += 128) {
            int iq = idx >> 6, d = idx & 63;
            qs[iq][d] = qbase[(i0 + ii + iq) * 128 + d];
        }
        __syncthreads();

        // sim for 8 rows (independent chains -> ILP)
        float s[8];
#pragma unroll
        for (int iq = 0; iq < 8; iq++) {
            const float4* q4 = (const float4*)qs[iq];
            float acc = 0.f;
#pragma unroll
            for (int dd = 0; dd < 16; dd++) {
                float4 qv = q4[dd];
                acc = fmaf(qv.x, kreg[dd * 4 + 0], acc);
                acc = fmaf(qv.y, kreg[dd * 4 + 1], acc);
                acc = fmaf(qv.z, kreg[dd * 4 + 2], acc);
                acc = fmaf(qv.w, kreg[dd * 4 + 3], acc);
            }
            s[iq] = fmaf(acc, 0.125f, biasrow[(i0 + ii + iq) * 128 + t]);
        }

        // interleaved max-reduce over 128
        float lm[8];
#pragma unroll
        for (int iq = 0; iq < 8; iq++) lm[iq] = s[iq];
#pragma unroll
        for (int o = 16; o > 0; o >>= 1)
#pragma unroll
            for (int iq = 0; iq < 8; iq++)
                lm[iq] = fmaxf(lm[iq], __shfl_xor_sync(0xffffffff, lm[iq], o));
        if (lane == 0)
#pragma unroll
            for (int iq = 0; iq < 8; iq++) wredm[iq][warp] = lm[iq];
        __syncthreads();

        float e[8], ls[8];
#pragma unroll
        for (int iq = 0; iq < 8; iq++) {
            float mx = fmaxf(fmaxf(wredm[iq][0], wredm[iq][1]),
                             fmaxf(wredm[iq][2], wredm[iq][3]));
            e[iq] = __expf(s[iq] - mx);
            ls[iq] = e[iq];
        }
        ((float4*)attn8[t])[0] = make_float4(e[0], e[1], e[2], e[3]);
        ((float4*)attn8[t])[1] = make_float4(e[4], e[5], e[6], e[7]);
#pragma unroll
        for (int o = 16; o > 0; o >>= 1)
#pragma unroll
            for (int iq = 0; iq < 8; iq++)
                ls[iq] += __shfl_xor_sync(0xffffffff, ls[iq], o);
        if (lane == 0)
#pragma unroll
            for (int iq = 0; iq < 8; iq++) wreds[iq][warp] = ls[iq];
        __syncthreads();

        float inv[8];
#pragma unroll
        for (int iq = 0; iq < 8; iq++)
            inv[iq] = 1.f / (wreds[iq][0] + wreds[iq][1] + wreds[iq][2] + wreds[iq][3]);

        // AV: thread (d, half) accumulates 8 rows at once
        int d = t & 63, half = t >> 6;
        const float*  vrow = vs + d * 129 + half * 64;
        const float4* arow = (const float4*)attn8[half * 64];
        float a0 = 0.f, a1 = 0.f, a2 = 0.f, a3 = 0.f;
        float a4 = 0.f, a5 = 0.f, a6 = 0.f, a7 = 0.f;
#pragma unroll
        for (int jj = 0; jj < 64; jj++) {
            float  vv  = vrow[jj];
            float4 av0 = arow[jj * 2];
            float4 av1 = arow[jj * 2 + 1];
            a0 = fmaf(av0.x, vv, a0);
            a1 = fmaf(av0.y, vv, a1);
            a2 = fmaf(av0.z, vv, a2);
            a3 = fmaf(av0.w, vv, a3);
            a4 = fmaf(av1.x, vv, a4);
            a5 = fmaf(av1.y, vv, a5);
            a6 = fmaf(av1.z, vv, a6);
            a7 = fmaf(av1.w, vv, a7);
        }
        ored[0][t] = a0; ored[1][t] = a1; ored[2][t] = a2; ored[3][t] = a3;
        ored[4][t] = a4; ored[5][t] = a5; ored[6][t] = a6; ored[7][t] = a7;
        __syncthreads();
        if (t < 64) {
#pragma unroll
            for (int iq = 0; iq < 8; iq++)
                g_attT[(b * 1024 + i0 + ii + iq) * 512 + h * 64 + t] =
                    (ored[iq][t] + ored[iq][64 + t]) * inv[iq];
        }
    }
}

// ---------------- K6: output projection — 2x2 register blocking ----------------
__global__ __launch_bounds__(256) void k_outproj(const float* __restrict__ wo,
                                                 const float* __restrict__ bo,
                                                 float* __restrict__ out) {
    int b  = blockIdx.z;
    int ty = threadIdx.y, tx = threadIdx.x;
    int o0 = blockIdx.y * 32;
    int p0 = blockIdx.x * 32;

    __shared__ float wos[32][17];
    __shared__ float ats[32][17];
    float a00 = 0.f, a01 = 0.f, a10 = 0.f, a11 = 0.f;
    for (int kt = 0; kt < 32; kt++) {
        wos[ty]     [tx] = wo[(o0 + ty)      * 512 + kt * 16 + tx];
        wos[ty + 16][tx] = wo[(o0 + ty + 16) * 512 + kt * 16 + tx];
        ats[ty]     [tx] = g_attT[(b * 1024 + p0 + ty)      * 512 + kt * 16 + tx];
        ats[ty + 16][tx] = g_attT[(b * 1024 + p0 + ty + 16) * 512 + kt * 16 + tx];
        __syncthreads();
#pragma unroll
        for (int kk = 0; kk < 16; kk++) {
            float wa = wos[ty][kk],      wb2 = wos[ty + 16][kk];
            float pa = ats[tx][kk],      pb  = ats[tx + 16][kk];
            a00 = fmaf(wa,  pa, a00);
            a01 = fmaf(wa,  pb, a01);
            a10 = fmaf(wb2, pa, a10);
            a11 = fmaf(wb2, pb, a11);
        }
        __syncthreads();
    }
    float bo0 = bo[o0 + ty], bo1 = bo[o0 + ty + 16];
    out[(b * 256 + o0 + ty)      * 1024 + p0 + tx]      = a00 + bo0;
    out[(b * 256 + o0 + ty)      * 1024 + p0 + tx + 16] = a01 + bo0;
    out[(b * 256 + o0 + ty + 16) * 1024 + p0 + tx]      = a10 + bo1;
    out[(b * 256 + o0 + ty + 16) * 1024 + p0 + tx + 16] = a11 + bo1;
}

// ---------------- launch ----------------
extern "C" void kernel_launch(void* const* d_in, const int* in_sizes, int n_in,
                              void* d_out, int out_size) {
    const float* x      = (const float*)d_in[0];
    const float* wq     = (const float*)d_in[1];
    const float* wk     = (const float*)d_in[2];
    const float* wv     = (const float*)d_in[3];
    const float* dww    = (const float*)d_in[4];
    const float* dwb    = (const float*)d_in[5];
    const float* pw     = (const float*)d_in[6];
    const float* cw0    = (const float*)d_in[7];
    const float* cb0    = (const float*)d_in[8];
    const float* cw1    = (const float*)d_in[9];
    const float* cb1    = (const float*)d_in[10];
    const float* cw2    = (const float*)d_in[11];
    const float* cb2    = (const float*)d_in[12];
    const float* wo     = (const float*)d_in[13];
    const float* bo     = (const float*)d_in[14];
    float* out = (float*)d_out;

    k_qproj  <<<dim3(64, 8),       128>>>(x, wq);
    k_offsets<<<dim3(128, 8),      128>>>(dww, dwb, pw);
    k_sample <<<dim3(16, 8),       128>>>(x, wk, wv);
    k_cpb    <<<2048,              256>>>(cw0, cb0, cw1, cb1, cw2, cb2);
    k_attn   <<<dim3(32, 8, 2),    128>>>();
    k_outproj<<<dim3(32, 8, 2), dim3(16, 16)>>>(wo, bo, out);
}

// round 17
// speedup vs baseline: 1.0967x; 1.0674x over previous
#include <cuda_runtime.h>
#include <math.h>

// ---------------- problem constants ----------------
#define BB 2
#define PQ 1024
#define PJ 128
#define NBG 8

// ---------------- scratch (static device mem; no allocs) ----------------
__device__ float g_qT [NBG * PQ * 128];      // (bg, p, o)
__device__ float g_grid[NBG * PJ * 3];       // normalized grid_kv
__device__ float g_k  [BB * 8 * 64 * PJ];
__device__ float g_v  [BB * 8 * 64 * PJ];
__device__ float g_bias[2 * NBG * PQ * PJ];  // [m][n][i][j]
__device__ float g_attT[BB * PQ * 512];      // (b, p, c=h*64+d)

// ---------------- K1: grouped 1x1 conv -> qT only (coalesced, 1 barrier) ----------------
__global__ __launch_bounds__(128) void k_qproj(const float* __restrict__ x,
                                               const float* __restrict__ wq) {
    int bg = blockIdx.y;
    int p0 = blockIdx.x * 16;
    int o  = threadIdx.x;
    int b = bg >> 2, g = bg & 3;

    float wr[64];
    const float4* wrow = (const float4*)(wq + (g * 128 + o) * 64);
#pragma unroll
    for (int i = 0; i < 16; i++) {
        float4 v4 = wrow[i];
        wr[i*4+0] = v4.x; wr[i*4+1] = v4.y; wr[i*4+2] = v4.z; wr[i*4+3] = v4.w;
    }

    __shared__ __align__(16) float xs[16 * 68];
    const float* xb = x + (b * 256 + g * 64) * 1024 + p0;
    for (int idx = o; idx < 1024; idx += 128) {
        int i = idx >> 4, pp = idx & 15;
        xs[pp * 68 + i] = xb[i * 1024 + pp];
    }
    __syncthreads();

#pragma unroll
    for (int pp = 0; pp < 16; pp++) {
        const float4* x4 = (const float4*)(xs + pp * 68);
        float s = 0.f;
#pragma unroll
        for (int i4 = 0; i4 < 16; i4++) {
            float4 xv = x4[i4];
            s = fmaf(wr[i4*4+0], xv.x, s);
            s = fmaf(wr[i4*4+1], xv.y, s);
            s = fmaf(wr[i4*4+2], xv.z, s);
            s = fmaf(wr[i4*4+3], xv.w, s);
        }
        g_qT[(bg * 1024 + p0 + pp) * 128 + o] = s;
    }
}

// ---------------- K2: depthwise conv (coalesced via qT) -> GELU -> pw -> tanh -> grid ----------------
__global__ __launch_bounds__(128) void k_offsets(const float* __restrict__ dww,
                                                 const float* __restrict__ dwb,
                                                 const float* __restrict__ pw) {
    int n  = blockIdx.y;
    int jj = blockIdx.x;
    int od = jj >> 6, oh = (jj >> 3) & 7, ow = jj & 7;
    int c  = threadIdx.x;
    int lane = c & 31, warp = c >> 5;

    __shared__ float dws[64 * 129];
    __shared__ float part[12];
    for (int idx = c; idx < 8192; idx += 128) {
        int cc = idx >> 6, kk = idx & 63;
        dws[kk * 129 + cc] = dww[idx];
    }
    __syncthreads();

    const float* qb = g_qT + n * 1024 * 128;
    float acc = 0.f;
#pragma unroll
    for (int kf = 0; kf < 4; kf++) {
        int fi = od * 2 - 1 + kf;
        if (fi < 0 || fi >= 4) continue;
#pragma unroll
        for (int kh = 0; kh < 4; kh++) {
            int hi = oh * 2 - 1 + kh;
            if (hi < 0 || hi >= 16) continue;
#pragma unroll
            for (int kw = 0; kw < 4; kw++) {
                int wi = ow * 2 - 1 + kw;
                if (wi < 0 || wi >= 16) continue;
                int sp = fi * 256 + hi * 16 + wi;
                acc = fmaf(qb[sp * 128 + c], dws[(kf * 16 + kh * 4 + kw) * 129 + c], acc);
            }
        }
    }
    float v  = acc + dwb[c];
    float ge = 0.5f * v * (1.0f + erff(v * 0.70710678118654752f));   // exact GELU

    float r0 = ge * pw[c], r1 = ge * pw[128 + c], r2 = ge * pw[256 + c];
#pragma unroll
    for (int o = 16; o > 0; o >>= 1) {
        r0 += __shfl_xor_sync(0xffffffff, r0, o);
        r1 += __shfl_xor_sync(0xffffffff, r1, o);
        r2 += __shfl_xor_sync(0xffffffff, r2, o);
    }
    if (lane == 0) { part[warp * 3 + 0] = r0; part[warp * 3 + 1] = r1; part[warp * 3 + 2] = r2; }
    __syncthreads();
    if (c < 3) {
        float tot = part[c] + part[3 + c] + part[6 + c] + part[9 + c];
        float off = tanhf(tot) * 2.0f;
        float basec = (c == 0) ? (float)od : (c == 1) ? (float)oh : (float)ow;
        float denom = (c == 0) ? 1.0f : 7.0f;
        g_grid[(n * 128 + jj) * 3 + c] = 2.0f * (basec + off) / denom - 1.0f;
    }
}

// ---------------- K3: trilinear gather + k/v projection (8 j per block, weights in regs) ----------------
__global__ __launch_bounds__(128) void k_sample(const float* __restrict__ x,
                                                const float* __restrict__ wk,
                                                const float* __restrict__ wv) {
    int n  = blockIdx.y;
    int jg = blockIdx.x;
    int b = n >> 2, g = n & 3;
    int t = threadIdx.x;

    float wkr[64], wvr[64];
    {
        const float4* wk4 = (const float4*)(wk + (g * 128 + t) * 64);
        const float4* wv4 = (const float4*)(wv + (g * 128 + t) * 64);
#pragma unroll
        for (int i = 0; i < 16; i++) {
            float4 a = wk4[i], c4 = wv4[i];
            wkr[i*4+0] = a.x;  wkr[i*4+1] = a.y;  wkr[i*4+2] = a.z;  wkr[i*4+3] = a.w;
            wvr[i*4+0] = c4.x; wvr[i*4+1] = c4.y; wvr[i*4+2] = c4.z; wvr[i*4+3] = c4.w;
        }
    }

    __shared__ float kvs[8][64];
    for (int u = t; u < 512; u += 128) {
        int jl = u >> 6, c = u & 63;
        int j = jg * 8 + jl;
        float g0 = g_grid[(n * 128 + j) * 3 + 0];
        float g1 = g_grid[(n * 128 + j) * 3 + 1];
        float g2 = g_grid[(n * 128 + j) * 3 + 2];
        float ix = ((g0 + 1.f) * 16.f - 1.f) * 0.5f;
        float iy = ((g1 + 1.f) * 16.f - 1.f) * 0.5f;
        float iz = ((g2 + 1.f) * 4.f  - 1.f) * 0.5f;
        float x0f = floorf(ix), y0f = floorf(iy), z0f = floorf(iz);
        float tx = ix - x0f, ty = iy - y0f, tz = iz - z0f;
        int x0 = (int)x0f, y0 = (int)y0f, z0 = (int)z0f;

        const float* vol = x + (b * 256 + g * 64 + c) * 1024;
        float s = 0.f;
#pragma unroll
        for (int dz = 0; dz < 2; dz++)
#pragma unroll
            for (int dy = 0; dy < 2; dy++)
#pragma unroll
                for (int dx = 0; dx < 2; dx++) {
                    int xc = x0 + dx, yc = y0 + dy, zc = z0 + dz;
                    float wgt = (dx ? tx : 1.f - tx) * (dy ? ty : 1.f - ty) * (dz ? tz : 1.f - tz);
                    if (xc >= 0 && xc < 16 && yc >= 0 && yc < 16 && zc >= 0 && zc < 4)
                        s = fmaf(vol[zc * 256 + yc * 16 + xc], wgt, s);
                }
        kvs[jl][c] = s;
    }
    __syncthreads();

    int h = g * 2 + (t >> 6);
    int d = t & 63;
    float* kout = g_k + ((b * 8 + h) * 64 + d) * 128 + jg * 8;
    float* vout = g_v + ((b * 8 + h) * 64 + d) * 128 + jg * 8;
    for (int jl = 0; jl < 8; jl++) {
        float sk = 0.f, sv = 0.f;
#pragma unroll
        for (int i = 0; i < 64; i++) {
            float kv = kvs[jl][i];
            sk = fmaf(kv, wkr[i], sk);
            sv = fmaf(kv, wvr[i], sv);
        }
        kout[jl] = sk;
        vout[jl] = sv;
    }
}

// ---------------- K4: CPB bias MLP — fi-quad threading: block=(n,hi,wi), thread=(j, chhalf),
//                  4 fi-pairs x 32 channels / thread, warp-uniform broadcast LDS ----------------
__global__ __launch_bounds__(256, 1) void k_cpb(const float* __restrict__ w0,
                                                const float* __restrict__ b0,
                                                const float* __restrict__ w1,
                                                const float* __restrict__ b1,
                                                const float* __restrict__ w2,
                                                const float* __restrict__ b2) {
    __shared__ __align__(16) float w1s[4096];
    __shared__ float w0s[192], b0s[64], b1s[64], w2s[128], b2s[2];
    __shared__ float part2[128 * 9];          // upper-half partial layer-2: [j][fi*2+o], stride 9
    int tid = threadIdx.x;
    for (int i = tid; i < 192;  i += 256) w0s[i] = w0[i];
    for (int i = tid; i < 64;   i += 256) { b0s[i] = b0[i]; b1s[i] = b1[i]; }
    for (int i = tid; i < 4096; i += 256) w1s[i] = w1[i];
    for (int i = tid; i < 128;  i += 256) w2s[i] = w2[i];
    if (tid < 2) b2s[tid] = b2[tid];
    __syncthreads();

    int n  = blockIdx.y;
    int hw = blockIdx.x;            // hi*16 + wi
    int hi = hw >> 4, wi = hw & 15;
    int j    = tid & 127;
    int chh  = tid >> 7;            // warp-group channel half (warps 0-3 -> 0, 4-7 -> 1)
    int ch0  = chh * 32;

    // features: t1,t2 shared across fi; t0 per fi
    float t0v[4], t1, t2;
    {
        float gq1 = 2.f * (float)hi / 15.f - 1.f;
        float gq2 = 2.f * (float)wi / 15.f - 1.f;
        float p1 = gq1 - g_grid[(n * 128 + j) * 3 + 1];
        float p2 = gq2 - g_grid[(n * 128 + j) * 3 + 2];
        t1 = copysignf(log1pf(fabsf(p1)), p1);
        t2 = copysignf(log1pf(fabsf(p2)), p2);
        float gr0 = g_grid[(n * 128 + j) * 3 + 0];
#pragma unroll
        for (int f = 0; f < 4; f++) {
            float gq0 = 2.f * (float)f / 3.f - 1.f;
            float p0 = gq0 - gr0;
            t0v[f] = copysignf(log1pf(fabsf(p0)), p0);
        }
    }

    // accumulators: 4 fi x 16 f32x2 (channels [ch0, ch0+32))
    unsigned long long acc[4][16];
#pragma unroll
    for (int c = 0; c < 16; c++) {
        unsigned long long bi;
        asm("mov.b64 %0, {%1, %2};" : "=l"(bi)
            : "f"(b1s[ch0 + 2 * c]), "f"(b1s[ch0 + 2 * c + 1]));
#pragma unroll
        for (int f = 0; f < 4; f++) acc[f][c] = bi;
    }

#pragma unroll 4
    for (int k = 0; k < 64; k++) {
        float w0k = w0s[k];
        float C = fmaf(t1, w0s[64 + k], fmaf(t2, w0s[128 + k], b0s[k]));
        unsigned long long h2[4];
#pragma unroll
        for (int f = 0; f < 4; f++) {
            float h = fmaxf(fmaf(t0v[f], w0k, C), 0.f);
            asm("mov.b64 %0, {%1, %1};" : "=l"(h2[f]) : "f"(h));
        }
        const ulonglong2* wrow = (const ulonglong2*)(w1s + k * 64 + ch0);  // warp-uniform
#pragma unroll
        for (int c = 0; c < 8; c++) {
            ulonglong2 wv = wrow[c];
#pragma unroll
            for (int f = 0; f < 4; f++) {
                asm("fma.rn.f32x2 %0, %1, %2, %0;" : "+l"(acc[f][2 * c])     : "l"(h2[f]), "l"(wv.x));
                asm("fma.rn.f32x2 %0, %1, %2, %0;" : "+l"(acc[f][2 * c + 1]) : "l"(h2[f]), "l"(wv.y));
            }
        }
    }

    // partial layer-2 over own 32 channels, all 4 fi
    float o0[4], o1[4];
#pragma unroll
    for (int f = 0; f < 4; f++) {
        float s0 = 0.f, s1 = 0.f;
#pragma unroll
        for (int c = 0; c < 16; c++) {
            int ch = ch0 + 2 * c;
            float lo, hi2;
            asm("mov.b64 {%0, %1}, %2;" : "=f"(lo), "=f"(hi2) : "l"(acc[f][c]));
            lo = fmaxf(lo, 0.f); hi2 = fmaxf(hi2, 0.f);
            s0 = fmaf(lo,  w2s[ch * 2 + 0], s0);
            s1 = fmaf(lo,  w2s[ch * 2 + 1], s1);
            s0 = fmaf(hi2, w2s[ch * 2 + 2], s0);
            s1 = fmaf(hi2, w2s[ch * 2 + 3], s1);
        }
        o0[f] = s0; o1[f] = s1;
    }

    // combine the two channel halves via smem
    if (chh == 1) {
#pragma unroll
        for (int f = 0; f < 4; f++) {
            part2[j * 9 + f * 2 + 0] = o0[f];
            part2[j * 9 + f * 2 + 1] = o1[f];
        }
    }
    __syncthreads();
    if (chh == 0) {
#pragma unroll
        for (int f = 0; f < 4; f++) {
            float r0 = o0[f] + part2[j * 9 + f * 2 + 0] + b2s[0];
            float r1 = o1[f] + part2[j * 9 + f * 2 + 1] + b2s[1];
            int i = f * 256 + hi * 16 + wi;
            g_bias[(        n * 1024 + i) * 128 + j] = r0;
            g_bias[((8 + n) * 1024 + i) * 128 + j]   = r1;
        }
    }
}

// ---------------- K5: attention — 4 i-rows per round, K in registers (R12 version) ----------------
__global__ __launch_bounds__(128) void k_attn() {
    int b = blockIdx.z, h = blockIdx.y;
    int i0 = blockIdx.x * 32;
    int g = h >> 1, m = h & 1;
    int n = b * 4 + g;
    int t = threadIdx.x;
    int lane = t & 31, warp = t >> 5;

    __shared__ float vs[64 * 129];
    __shared__ __align__(16) float qs[4][64];
    __shared__ __align__(16) float attn4[128][4];
    __shared__ float wredm[4][4], wreds[4][4];
    __shared__ float ored[4][128];

    const float* kb = g_k + (b * 8 + h) * 64 * 128;
    const float* vb = g_v + (b * 8 + h) * 64 * 128;

    float kreg[64];
#pragma unroll
    for (int d = 0; d < 64; d++) kreg[d] = kb[d * 128 + t];

    for (int idx = t; idx < 8192; idx += 128) {
        int d = idx >> 7, jc = idx & 127;
        vs[d * 129 + jc] = vb[idx];
    }
    const float* biasrow = g_bias + ((m * 8 + n) * 1024) * 128;
    const float* qbase = g_qT + ((b * 4 + g) * 1024) * 128 + m * 64;

    for (int ii = 0; ii < 32; ii += 4) {
        __syncthreads();
        for (int idx = t; idx < 256; idx += 128) {
            int iq = idx >> 6, d = idx & 63;
            qs[iq][d] = qbase[(i0 + ii + iq) * 128 + d];
        }
        __syncthreads();

        float s[4];
#pragma unroll
        for (int iq = 0; iq < 4; iq++) {
            const float4* q4 = (const float4*)qs[iq];
            float acc = 0.f;
#pragma unroll
            for (int dd = 0; dd < 16; dd++) {
                float4 qv = q4[dd];
                acc = fmaf(qv.x, kreg[dd * 4 + 0], acc);
                acc = fmaf(qv.y, kreg[dd * 4 + 1], acc);
                acc = fmaf(qv.z, kreg[dd * 4 + 2], acc);
                acc = fmaf(qv.w, kreg[dd * 4 + 3], acc);
            }
            s[iq] = fmaf(acc, 0.125f, biasrow[(i0 + ii + iq) * 128 + t]);
        }

        float lm[4];
#pragma unroll
        for (int iq = 0; iq < 4; iq++) lm[iq] = s[iq];
#pragma unroll
        for (int o = 16; o > 0; o >>= 1)
#pragma unroll
            for (int iq = 0; iq < 4; iq++)
                lm[iq] = fmaxf(lm[iq], __shfl_xor_sync(0xffffffff, lm[iq], o));
        if (lane == 0)
#pragma unroll
            for (int iq = 0; iq < 4; iq++) wredm[iq][warp] = lm[iq];
        __syncthreads();

        float e[4], ls[4];
#pragma unroll
        for (int iq = 0; iq < 4; iq++) {
            float mx = fmaxf(fmaxf(wredm[iq][0], wredm[iq][1]),
                             fmaxf(wredm[iq][2], wredm[iq][3]));
            e[iq] = __expf(s[iq] - mx);
            ls[iq] = e[iq];
        }
        *(float4*)attn4[t] = make_float4(e[0], e[1], e[2], e[3]);
#pragma unroll
        for (int o = 16; o > 0; o >>= 1)
#pragma unroll
            for (int iq = 0; iq < 4; iq++)
                ls[iq] += __shfl_xor_sync(0xffffffff, ls[iq], o);
        if (lane == 0)
#pragma unroll
            for (int iq = 0; iq < 4; iq++) wreds[iq][warp] = ls[iq];
        __syncthreads();

        float inv[4];
#pragma unroll
        for (int iq = 0; iq < 4; iq++)
            inv[iq] = 1.f / (wreds[iq][0] + wreds[iq][1] + wreds[iq][2] + wreds[iq][3]);

        int d = t & 63, half = t >> 6;
        const float*  vrow = vs + d * 129 + half * 64;
        const float4* arow = (const float4*)attn4[half * 64];
        float a0 = 0.f, a1 = 0.f, a2 = 0.f, a3 = 0.f;
#pragma unroll
        for (int jj = 0; jj < 64; jj++) {
            float  vv = vrow[jj];
            float4 av = arow[jj];
            a0 = fmaf(av.x, vv, a0);
            a1 = fmaf(av.y, vv, a1);
            a2 = fmaf(av.z, vv, a2);
            a3 = fmaf(av.w, vv, a3);
        }
        ored[0][t] = a0; ored[1][t] = a1; ored[2][t] = a2; ored[3][t] = a3;
        __syncthreads();
        if (t < 64) {
#pragma unroll
            for (int iq = 0; iq < 4; iq++)
                g_attT[(b * 1024 + i0 + ii + iq) * 512 + h * 64 + t] =
                    (ored[iq][t] + ored[iq][64 + t]) * inv[iq];
        }
    }
}

// ---------------- K6: output projection — 2x2 register blocking ----------------
__global__ __launch_bounds__(256) void k_outproj(const float* __restrict__ wo,
                                                 const float* __restrict__ bo,
                                                 float* __restrict__ out) {
    int b  = blockIdx.z;
    int ty = threadIdx.y, tx = threadIdx.x;
    int o0 = blockIdx.y * 32;
    int p0 = blockIdx.x * 32;

    __shared__ float wos[32][17];
    __shared__ float ats[32][17];
    float a00 = 0.f, a01 = 0.f, a10 = 0.f, a11 = 0.f;
    for (int kt = 0; kt < 32; kt++) {
        wos[ty]     [tx] = wo[(o0 + ty)      * 512 + kt * 16 + tx];
        wos[ty + 16][tx] = wo[(o0 + ty + 16) * 512 + kt * 16 + tx];
        ats[ty]     [tx] = g_attT[(b * 1024 + p0 + ty)      * 512 + kt * 16 + tx];
        ats[ty + 16][tx] = g_attT[(b * 1024 + p0 + ty + 16) * 512 + kt * 16 + tx];
        __syncthreads();
#pragma unroll
        for (int kk = 0; kk < 16; kk++) {
            float wa = wos[ty][kk],      wb2 = wos[ty + 16][kk];
            float pa = ats[tx][kk],      pb  = ats[tx + 16][kk];
            a00 = fmaf(wa,  pa, a00);
            a01 = fmaf(wa,  pb, a01);
            a10 = fmaf(wb2, pa, a10);
            a11 = fmaf(wb2, pb, a11);
        }
        __syncthreads();
    }
    float bo0 = bo[o0 + ty], bo1 = bo[o0 + ty + 16];
    out[(b * 256 + o0 + ty)      * 1024 + p0 + tx]      = a00 + bo0;
    out[(b * 256 + o0 + ty)      * 1024 + p0 + tx + 16] = a01 + bo0;
    out[(b * 256 + o0 + ty + 16) * 1024 + p0 + tx]      = a10 + bo1;
    out[(b * 256 + o0 + ty + 16) * 1024 + p0 + tx + 16] = a11 + bo1;
}

// ---------------- launch ----------------
extern "C" void kernel_launch(void* const* d_in, const int* in_sizes, int n_in,
                              void* d_out, int out_size) {
    const float* x      = (const float*)d_in[0];
    const float* wq     = (const float*)d_in[1];
    const float* wk     = (const float*)d_in[2];
    const float* wv     = (const float*)d_in[3];
    const float* dww    = (const float*)d_in[4];
    const float* dwb    = (const float*)d_in[5];
    const float* pw     = (const float*)d_in[6];
    const float* cw0    = (const float*)d_in[7];
    const float* cb0    = (const float*)d_in[8];
    const float* cw1    = (const float*)d_in[9];
    const float* cb1    = (const float*)d_in[10];
    const float* cw2    = (const float*)d_in[11];
    const float* cb2    = (const float*)d_in[12];
    const float* wo     = (const float*)d_in[13];
    const float* bo     = (const float*)d_in[14];
    float* out = (float*)d_out;

    k_qproj  <<<dim3(64, 8),       128>>>(x, wq);
    k_offsets<<<dim3(128, 8),      128>>>(dww, dwb, pw);
    k_sample <<<dim3(16, 8),       128>>>(x, wk, wv);
    k_cpb    <<<dim3(256, 8),      256>>>(cw0, cb0, cw1, cb1, cw2, cb2);
    k_attn   <<<dim3(32, 8, 2),    128>>>();
    k_outproj<<<dim3(32, 8, 2), dim3(16, 16)>>>(wo, bo, out);
}